// round 4
// baseline (speedup 1.0000x reference)
#include <cuda_runtime.h>
#include <math.h>

typedef unsigned long long ull;

#define TT 2048
#define BB 64
#define II 128
#define HH 256
#define NBLK 128
#define NTHR 512
#define HXS  68             /* staged h row stride: conflict-free LDS.128 */
#define WSS  12             /* ws row stride (8 cols + 4 pad): conflict-free LDS.128 */

// ---- device scratch (static) ----
__device__ __align__(16) float g_xT[(size_t)TT * II * BB];        // [t][i][b]
__device__ __align__(16) float g_gx[(size_t)TT * BB * NBLK * 8];  // [t][b][jblk][c]
__device__ __align__(16) float g_hbuf[2][HH * BB];                // [buf][j][b]
__device__ unsigned g_bar = 0;
__device__ unsigned g_gen = 0;

// ---- helpers ----
__device__ __forceinline__ void cp16(float* smem_dst, const float* gmem_src) {
    unsigned s = (unsigned)__cvta_generic_to_shared(smem_dst);
    asm volatile("cp.async.cg.shared.global [%0], [%1], 16;" :: "r"(s), "l"(gmem_src));
}
#define CP_COMMIT() asm volatile("cp.async.commit_group;" ::: "memory")
#define CP_WAIT0()  asm volatile("cp.async.wait_group 0;" ::: "memory")
#define CP_WAIT1()  asm volatile("cp.async.wait_group 1;" ::: "memory")

__device__ __forceinline__ ull pk2(float v) {            // (v, v) packed
    ull r; unsigned u = __float_as_uint(v);
    asm("mov.b64 %0, {%1, %1};" : "=l"(r) : "r"(u));
    return r;
}
__device__ __forceinline__ void fma2(ull& d, ull a, ull b) {
    asm("fma.rn.f32x2 %0, %1, %2, %0;" : "+l"(d) : "l"(a), "l"(b));
}
__device__ __forceinline__ ull add2(ull a, ull b) {
    ull r; asm("add.rn.f32x2 %0, %1, %2;" : "=l"(r) : "l"(a), "l"(b));
    return r;
}

// ============================================================
// Kernel 1: transpose x [b][t][i] -> g_xT [t][i][b]
// ============================================================
__global__ void __launch_bounds__(256) xpose_kernel(const float* __restrict__ x)
{
    __shared__ float xs[BB * (II + 1)];
    const int t = blockIdx.x;
    for (int idx = threadIdx.x; idx < BB * II; idx += 256) {
        int b = idx >> 7, i = idx & 127;
        xs[b * (II + 1) + i] = x[((size_t)b * TT + t) * II + i];
    }
    __syncthreads();
    float* dst = g_xT + (size_t)t * (II * BB);
    for (int idx = threadIdx.x; idx < II * BB; idx += 256) {
        int i = idx >> 6, b = idx & 63;
        dst[idx] = xs[b * (II + 1) + i];
    }
}

// ============================================================
// Kernel 2: precompute gx = x_t . W_x for all t.
// grid = (t=2048, cb=8); block 512. Col-block cb covers jblk 16cb..16cb+15
// (128 local cols: col = bid_l*8 + g*2 + jj, h = 32cb + 2*bid_l + jj).
// Thread (bq = tid>>5, lane): 4b x 4c tile (cols 4*lane..4*lane+3), k=0..127.
// SMEM: xs[128][68] + ws2[128][128]
// ============================================================
#define GX_XS 0
#define GX_WS (II * HXS)                        /* 8704 floats */
#define GX_SMEM_FLOATS (GX_WS + II * 128)
#define GX_SMEM_BYTES  (GX_SMEM_FLOATS * 4)

__global__ void __launch_bounds__(512) gx_kernel(const float* __restrict__ Wx)
{
    extern __shared__ float sm[];
    float* xs  = sm + GX_XS;
    float* ws2 = sm + GX_WS;

    const int t    = blockIdx.x;
    const int cb   = blockIdx.y;
    const int tid  = threadIdx.x;
    const int lane = tid & 31;
    const int bq   = tid >> 5;

    // stage x slab [i][b] via cp.async
    {
        const float* src = g_xT + (size_t)t * (II * BB);
        #pragma unroll
        for (int i = 0; i < 4; ++i) {
            int idx = tid + i * 512;
            int row = idx >> 4, c4 = (idx & 15) << 2;
            cp16(xs + row * HXS + c4, src + idx * 4);
        }
        CP_COMMIT();
    }
    // stage weight slice: ws2[k*128 + col]
    #pragma unroll
    for (int j = 0; j < 32; ++j) {
        int idx = tid + j * 512;
        int k = idx >> 7, rem = idx & 127;
        int g = rem >> 5, hl = rem & 31;
        int col = ((hl >> 1) << 3) + (g << 1) + (hl & 1);
        ws2[k * 128 + col] = __ldg(Wx + ((size_t)g * II + k) * HH + (cb << 5) + hl);
    }
    CP_WAIT0();
    __syncthreads();

    ull acc2[8];
    #pragma unroll
    for (int i = 0; i < 8; ++i) acc2[i] = 0ull;

    const float* xp = xs + (bq << 2);
    const float* wp = ws2 + (lane << 2);
    #pragma unroll 4
    for (int k = 0; k < II; ++k) {
        float4 hv = *(const float4*)(xp + k * HXS);      // warp-uniform broadcast
        ulonglong2 wv = *(const ulonglong2*)(wp + k * 128);
        ull h0 = pk2(hv.x), h1 = pk2(hv.y), h2 = pk2(hv.z), h3 = pk2(hv.w);
        fma2(acc2[0], h0, wv.x); fma2(acc2[1], h0, wv.y);
        fma2(acc2[2], h1, wv.x); fma2(acc2[3], h1, wv.y);
        fma2(acc2[4], h2, wv.x); fma2(acc2[5], h2, wv.y);
        fma2(acc2[6], h3, wv.x); fma2(acc2[7], h3, wv.y);
    }

    // write gx[t][b][jblk][c]: thread's cols = 4*lane..4*lane+3
    const int bid = (cb << 4) + (lane >> 1);
    const int c0  = (lane & 1) << 2;
    #pragma unroll
    for (int r = 0; r < 4; ++r) {
        int b = (bq << 2) + r;
        ulonglong2 v; v.x = acc2[r * 2]; v.y = acc2[r * 2 + 1];
        *(ulonglong2*)(g_gx + ((((size_t)t * BB + b) * NBLK + bid) << 3) + c0) = v;
    }
}

// ============================================================
// Kernel 3: persistent LSTM recurrence (h-part only).
// 128 blocks x 512 thr. Block bid owns j0=2*bid (8 gate cols).
// Warp w: batches 4w..4w+3. Lane l: k-slice {l, l+32, ..., l+224}.
// SMEM: ws[256*12] @0, hb[256*68] @3072, bs[8]
// ============================================================
#define SM_WS 0
#define SM_H  (HH * WSS)              /* 3072 */
#define SM_BS (SM_H + HH * HXS)       /* 20480 */
#define SMEM_FLOATS (SM_BS + 8)
#define SMEM_BYTES  (SMEM_FLOATS * 4)

__global__ void __launch_bounds__(NTHR, 1) lstm_kernel(
    const float* __restrict__ Wh, const float* __restrict__ bias,
    float* __restrict__ out)
{
    extern __shared__ float sm[];
    float* ws = sm + SM_WS;
    float* hb = sm + SM_H;
    float* bs = sm + SM_BS;

    const int tid  = threadIdx.x;
    const int w    = tid >> 5;
    const int lane = tid & 31;
    const int j0   = blockIdx.x * 2;
    const int bw   = w << 2;

    // one-time: W_h slice ws[k*12 + c]
    for (int idx = tid; idx < HH * 8; idx += NTHR) {
        int k = idx >> 3, c = idx & 7;
        ws[k * WSS + c] = Wh[(((size_t)(c >> 1)) * HH + k) * HH + (j0 + (c & 1))];
    }
    if (tid < 8) bs[tid] = bias[(tid >> 1) * HH + j0 + (tid & 1)];

    float creg = 0.f;
    const int  jj   = lane & 1;
    const int  myb  = (w << 2) + (lane >> 3);
    const int  base = lane & 24;
    const bool upd  = (lane & 7) < 2;
    const float myBias = bs ? 0.f : 0.f;   // placeholder (bs read after sync below)

    __syncthreads();
    const float biasv = bs[lane & 7];

    // gx address for this lane's output (b = 4w + (lane>>3), jblk = blockIdx.x, c = lane&7)
    const float* gxp = g_gx
        + ((((size_t)0 * BB + myb) * NBLK + blockIdx.x) << 3) + (lane & 7);
    const size_t gxstep = (size_t)BB * NBLK * 8;

    for (int t = 0; t < TT; ++t) {
        // ---- issue gx load early (no peer dependence) ----
        float gxv = __ldg(gxp + (size_t)t * gxstep);

        if (t > 0) {
            // ---- grid barrier ----
            __syncthreads();
            if (tid == 0) {
                unsigned gen = *(volatile unsigned*)&g_gen;
                unsigned ticket = atomicAdd(&g_bar, 1u);
                if (ticket == NBLK - 1) {
                    g_bar = 0;
                    __threadfence();
                    atomicExch(&g_gen, gen + 1u);
                } else {
                    while (*(volatile unsigned*)&g_gen == gen) { }
                }
            }
            __syncthreads();

            // ---- stage h in two halves (rows 0..127 | 128..255) ----
            const float* src = g_hbuf[t & 1];
            #pragma unroll
            for (int i = 0; i < 4; ++i) {
                int idx = tid + i * NTHR;
                int row = idx >> 4, c4 = (idx & 15) << 2;
                cp16(hb + row * HXS + c4, src + idx * 4);
            }
            CP_COMMIT();
            #pragma unroll
            for (int i = 4; i < 8; ++i) {
                int idx = tid + i * NTHR;
                int row = idx >> 4, c4 = (idx & 15) << 2;
                cp16(hb + row * HXS + c4, src + idx * 4);
            }
            CP_COMMIT();
        }

        ull acc2[16];
        #pragma unroll
        for (int i = 0; i < 16; ++i) acc2[i] = 0ull;

        if (t > 0) {
            // ---- half A ----
            CP_WAIT1();
            __syncthreads();
            #pragma unroll
            for (int u = 0; u < 4; ++u) {
                const int k = lane + (u << 5);
                float4 hv = *(const float4*)(hb + k * HXS + bw);
                ulonglong2 w0 = *(const ulonglong2*)(ws + k * WSS);
                ulonglong2 w1 = *(const ulonglong2*)(ws + k * WSS + 4);
                ull h0 = pk2(hv.x), h1 = pk2(hv.y), h2 = pk2(hv.z), h3 = pk2(hv.w);
                fma2(acc2[0],  h0, w0.x); fma2(acc2[1],  h0, w0.y);
                fma2(acc2[2],  h0, w1.x); fma2(acc2[3],  h0, w1.y);
                fma2(acc2[4],  h1, w0.x); fma2(acc2[5],  h1, w0.y);
                fma2(acc2[6],  h1, w1.x); fma2(acc2[7],  h1, w1.y);
                fma2(acc2[8],  h2, w0.x); fma2(acc2[9],  h2, w0.y);
                fma2(acc2[10], h2, w1.x); fma2(acc2[11], h2, w1.y);
                fma2(acc2[12], h3, w0.x); fma2(acc2[13], h3, w0.y);
                fma2(acc2[14], h3, w1.x); fma2(acc2[15], h3, w1.y);
            }
            // ---- half B ----
            CP_WAIT0();
            __syncthreads();
            #pragma unroll
            for (int u = 4; u < 8; ++u) {
                const int k = lane + (u << 5);
                float4 hv = *(const float4*)(hb + k * HXS + bw);
                ulonglong2 w0 = *(const ulonglong2*)(ws + k * WSS);
                ulonglong2 w1 = *(const ulonglong2*)(ws + k * WSS + 4);
                ull h0 = pk2(hv.x), h1 = pk2(hv.y), h2 = pk2(hv.z), h3 = pk2(hv.w);
                fma2(acc2[0],  h0, w0.x); fma2(acc2[1],  h0, w0.y);
                fma2(acc2[2],  h0, w1.x); fma2(acc2[3],  h0, w1.y);
                fma2(acc2[4],  h1, w0.x); fma2(acc2[5],  h1, w0.y);
                fma2(acc2[6],  h1, w1.x); fma2(acc2[7],  h1, w1.y);
                fma2(acc2[8],  h2, w0.x); fma2(acc2[9],  h2, w0.y);
                fma2(acc2[10], h2, w1.x); fma2(acc2[11], h2, w1.y);
                fma2(acc2[12], h3, w0.x); fma2(acc2[13], h3, w0.y);
                fma2(acc2[14], h3, w1.x); fma2(acc2[15], h3, w1.y);
            }
        }

        // ---- packed butterfly reduce-scatter ----
        #pragma unroll
        for (int n = 16; n >= 2; n >>= 1) {
            const int m = n >> 1;
            #pragma unroll
            for (int s = 0; s < m; ++s) {
                ull lo = acc2[s], hi = acc2[s + m];
                ull send = (lane & n) ? lo : hi;
                ull keep = (lane & n) ? hi : lo;
                acc2[s] = add2(keep, __shfl_xor_sync(0xffffffffu, send, n));
            }
        }
        float pre;
        {
            unsigned u0, u1;
            asm("mov.b64 {%0, %1}, %2;" : "=r"(u0), "=r"(u1) : "l"(acc2[0]));
            float a0 = __uint_as_float(u0), a1 = __uint_as_float(u1);
            float send = (lane & 1) ? a0 : a1;
            float keep = (lane & 1) ? a1 : a0;
            pre = keep + __shfl_xor_sync(0xffffffffu, send, 1);
        }
        pre += gxv + biasv;

        // ---- gather gates, cell, write h ----
        float pf = __shfl_sync(0xffffffffu, pre, base | (2 + jj));
        float pg = __shfl_sync(0xffffffffu, pre, base | (4 + jj));
        float po = __shfl_sync(0xffffffffu, pre, base | (6 + jj));
        if (upd) {
            float ig = 1.f / (1.f + __expf(-pre));
            float fg = 1.f / (1.f + __expf(-pf));
            float gg = tanhf(pg);
            float og = 1.f / (1.f + __expf(-po));
            creg = fg * creg + ig * gg;
            float hv = og * tanhf(creg);
            g_hbuf[(t & 1) ^ 1][(j0 + jj) * BB + myb] = hv;
            out[((size_t)myb * TT + t) * HH + (j0 + jj)] = hv;
        }
        __threadfence();
    }
}

// ============================================================
extern "C" void kernel_launch(void* const* d_in, const int* in_sizes, int n_in,
                              void* d_out, int out_size)
{
    const float* x  = (const float*)d_in[0];   // [B, T, I]
    const float* Wx = (const float*)d_in[1];   // [4, I, H]
    const float* Wh = (const float*)d_in[2];   // [4, H, H]
    const float* b  = (const float*)d_in[3];   // [4, H]
    float* out = (float*)d_out;                // [B, T, H]

    cudaFuncSetAttribute(gx_kernel,
                         cudaFuncAttributeMaxDynamicSharedMemorySize, GX_SMEM_BYTES);
    cudaFuncSetAttribute(lstm_kernel,
                         cudaFuncAttributeMaxDynamicSharedMemorySize, SMEM_BYTES);

    xpose_kernel<<<TT, 256>>>(x);
    gx_kernel<<<dim3(TT, 8), 512, GX_SMEM_BYTES>>>(Wx);
    lstm_kernel<<<NBLK, NTHR, SMEM_BYTES>>>(Wh, b, out);
}

// round 5
// speedup vs baseline: 1.1019x; 1.1019x over previous
#include <cuda_runtime.h>
#include <math.h>

typedef unsigned long long ull;

#define TT 2048
#define BB 64
#define II 128
#define HH 256
#define NBLK 128
#define NTHR 512
#define HXS  68             /* staged h row stride: conflict-free LDS.128 */
#define WSS  12             /* ws row stride (8 cols + 4 pad): conflict-free LDS.128 */

// ---- device scratch (static) ----
__device__ __align__(16) float g_xT[(size_t)TT * II * BB];        // [t][i][b]
__device__ __align__(16) float g_gx[(size_t)TT * BB * NBLK * 8];  // [t][b][jblk][c]
__device__ __align__(16) float g_hbuf[2][HH * BB];                // [buf][j][b]
__device__ __align__(128) unsigned g_flags[NBLK * 32];            // 1 flag / 128B line

// ---- helpers ----
__device__ __forceinline__ void cp16(float* smem_dst, const float* gmem_src) {
    unsigned s = (unsigned)__cvta_generic_to_shared(smem_dst);
    asm volatile("cp.async.cg.shared.global [%0], [%1], 16;" :: "r"(s), "l"(gmem_src));
}
#define CP_COMMIT() asm volatile("cp.async.commit_group;" ::: "memory")
#define CP_WAIT0()  asm volatile("cp.async.wait_group 0;" ::: "memory")
#define CP_WAIT1()  asm volatile("cp.async.wait_group 1;" ::: "memory")

__device__ __forceinline__ ull pk2(float v) {
    ull r; unsigned u = __float_as_uint(v);
    asm("mov.b64 %0, {%1, %1};" : "=l"(r) : "r"(u));
    return r;
}
__device__ __forceinline__ void fma2(ull& d, ull a, ull b) {
    asm("fma.rn.f32x2 %0, %1, %2, %0;" : "+l"(d) : "l"(a), "l"(b));
}
__device__ __forceinline__ ull add2(ull a, ull b) {
    ull r; asm("add.rn.f32x2 %0, %1, %2;" : "=l"(r) : "l"(a), "l"(b));
    return r;
}

// ============================================================
// Kernel 1: transpose x [b][t][i] -> g_xT [t][i][b]
// ============================================================
__global__ void __launch_bounds__(256) xpose_kernel(const float* __restrict__ x)
{
    __shared__ float xs[BB * (II + 1)];
    const int t = blockIdx.x;
    for (int idx = threadIdx.x; idx < BB * II; idx += 256) {
        int b = idx >> 7, i = idx & 127;
        xs[b * (II + 1) + i] = x[((size_t)b * TT + t) * II + i];
    }
    __syncthreads();
    float* dst = g_xT + (size_t)t * (II * BB);
    for (int idx = threadIdx.x; idx < II * BB; idx += 256) {
        int i = idx >> 6, b = idx & 63;
        dst[idx] = xs[b * (II + 1) + i];
    }
}

// ============================================================
// Kernel 2: precompute gx = x_t . W_x for all t.
// grid = (t=2048, cb=8); block 512. Also resets barrier flags
// (kernel boundary orders the reset before lstm_kernel).
// ============================================================
#define GX_XS 0
#define GX_WS (II * HXS)
#define GX_SMEM_FLOATS (GX_WS + II * 128)
#define GX_SMEM_BYTES  (GX_SMEM_FLOATS * 4)

__global__ void __launch_bounds__(512) gx_kernel(const float* __restrict__ Wx)
{
    extern __shared__ float sm[];
    float* xs  = sm + GX_XS;
    float* ws2 = sm + GX_WS;

    const int t    = blockIdx.x;
    const int cb   = blockIdx.y;
    const int tid  = threadIdx.x;
    const int lane = tid & 31;
    const int bq   = tid >> 5;

    if (t == 0 && cb == 0 && tid < NBLK)       // reset barrier flags (replay safety)
        g_flags[tid << 5] = 0u;

    {
        const float* src = g_xT + (size_t)t * (II * BB);
        #pragma unroll
        for (int i = 0; i < 4; ++i) {
            int idx = tid + i * 512;
            int row = idx >> 4, c4 = (idx & 15) << 2;
            cp16(xs + row * HXS + c4, src + idx * 4);
        }
        CP_COMMIT();
    }
    #pragma unroll
    for (int j = 0; j < 32; ++j) {
        int idx = tid + j * 512;
        int k = idx >> 7, rem = idx & 127;
        int g = rem >> 5, hl = rem & 31;
        int col = ((hl >> 1) << 3) + (g << 1) + (hl & 1);
        ws2[k * 128 + col] = __ldg(Wx + ((size_t)g * II + k) * HH + (cb << 5) + hl);
    }
    CP_WAIT0();
    __syncthreads();

    ull acc2[8];
    #pragma unroll
    for (int i = 0; i < 8; ++i) acc2[i] = 0ull;

    const float* xp = xs + (bq << 2);
    const float* wp = ws2 + (lane << 2);
    #pragma unroll 4
    for (int k = 0; k < II; ++k) {
        float4 hv = *(const float4*)(xp + k * HXS);
        ulonglong2 wv = *(const ulonglong2*)(wp + k * 128);
        ull h0 = pk2(hv.x), h1 = pk2(hv.y), h2 = pk2(hv.z), h3 = pk2(hv.w);
        fma2(acc2[0], h0, wv.x); fma2(acc2[1], h0, wv.y);
        fma2(acc2[2], h1, wv.x); fma2(acc2[3], h1, wv.y);
        fma2(acc2[4], h2, wv.x); fma2(acc2[5], h2, wv.y);
        fma2(acc2[6], h3, wv.x); fma2(acc2[7], h3, wv.y);
    }

    const int bid = (cb << 4) + (lane >> 1);
    const int c0  = (lane & 1) << 2;
    #pragma unroll
    for (int r = 0; r < 4; ++r) {
        int b = (bq << 2) + r;
        ulonglong2 v; v.x = acc2[r * 2]; v.y = acc2[r * 2 + 1];
        *(ulonglong2*)(g_gx + ((((size_t)t * BB + b) * NBLK + bid) << 3) + c0) = v;
    }
}

// ============================================================
// Kernel 3: persistent LSTM recurrence (h-part only).
// Distributed-flag grid barrier: no atomics, no threadfence.
// ============================================================
#define SM_WS 0
#define SM_H  (HH * WSS)
#define SM_BS (SM_H + HH * HXS)
#define SMEM_FLOATS (SM_BS + 8)
#define SMEM_BYTES  (SMEM_FLOATS * 4)

__global__ void __launch_bounds__(NTHR, 1) lstm_kernel(
    const float* __restrict__ Wh, const float* __restrict__ bias,
    float* __restrict__ out)
{
    extern __shared__ float sm[];
    float* ws = sm + SM_WS;
    float* hb = sm + SM_H;
    float* bs = sm + SM_BS;

    const int tid  = threadIdx.x;
    const int w    = tid >> 5;
    const int lane = tid & 31;
    const int j0   = blockIdx.x * 2;
    const int bw   = w << 2;

    for (int idx = tid; idx < HH * 8; idx += NTHR) {
        int k = idx >> 3, c = idx & 7;
        ws[k * WSS + c] = Wh[(((size_t)(c >> 1)) * HH + k) * HH + (j0 + (c & 1))];
    }
    if (tid < 8) bs[tid] = bias[(tid >> 1) * HH + j0 + (tid & 1)];

    float creg = 0.f;
    const int  jj   = lane & 1;
    const int  myb  = (w << 2) + (lane >> 3);
    const int  base = lane & 24;
    const bool upd  = (lane & 7) < 2;

    __syncthreads();
    const float biasv = bs[lane & 7];

    const float* gxp = g_gx + (((size_t)myb * NBLK + blockIdx.x) << 3) + (lane & 7);
    const size_t gxstep = (size_t)BB * NBLK * 8;

    unsigned* myflag = g_flags + (blockIdx.x << 5);
    const unsigned* pollflag = g_flags + ((tid & 127) << 5);

    for (int t = 0; t < TT; ++t) {
        float gxv = __ldg(gxp + (size_t)t * gxstep);   // early, hides DRAM latency

        if (t > 0) {
            // ---- grid barrier: distributed flags, generation = t ----
            __syncthreads();                            // step t-1 stores done
            if (tid == 0)
                asm volatile("st.release.gpu.global.u32 [%0], %1;"
                             :: "l"(myflag), "r"((unsigned)t) : "memory");
            if (tid < NBLK) {
                unsigned v;
                do {
                    asm volatile("ld.acquire.gpu.global.u32 %0, [%1];"
                                 : "=r"(v) : "l"(pollflag) : "memory");
                } while (v < (unsigned)t);
            }
            __syncthreads();

            // ---- stage h in two halves (rows 0..127 | 128..255) ----
            const float* src = g_hbuf[t & 1];
            #pragma unroll
            for (int i = 0; i < 4; ++i) {
                int idx = tid + i * NTHR;
                int row = idx >> 4, c4 = (idx & 15) << 2;
                cp16(hb + row * HXS + c4, src + idx * 4);
            }
            CP_COMMIT();
            #pragma unroll
            for (int i = 4; i < 8; ++i) {
                int idx = tid + i * NTHR;
                int row = idx >> 4, c4 = (idx & 15) << 2;
                cp16(hb + row * HXS + c4, src + idx * 4);
            }
            CP_COMMIT();
        }

        ull acc2[16];
        #pragma unroll
        for (int i = 0; i < 16; ++i) acc2[i] = 0ull;

        if (t > 0) {
            CP_WAIT1();
            __syncthreads();
            #pragma unroll
            for (int u = 0; u < 4; ++u) {
                const int k = lane + (u << 5);
                float4 hv = *(const float4*)(hb + k * HXS + bw);
                ulonglong2 w0 = *(const ulonglong2*)(ws + k * WSS);
                ulonglong2 w1 = *(const ulonglong2*)(ws + k * WSS + 4);
                ull h0 = pk2(hv.x), h1 = pk2(hv.y), h2 = pk2(hv.z), h3 = pk2(hv.w);
                fma2(acc2[0],  h0, w0.x); fma2(acc2[1],  h0, w0.y);
                fma2(acc2[2],  h0, w1.x); fma2(acc2[3],  h0, w1.y);
                fma2(acc2[4],  h1, w0.x); fma2(acc2[5],  h1, w0.y);
                fma2(acc2[6],  h1, w1.x); fma2(acc2[7],  h1, w1.y);
                fma2(acc2[8],  h2, w0.x); fma2(acc2[9],  h2, w0.y);
                fma2(acc2[10], h2, w1.x); fma2(acc2[11], h2, w1.y);
                fma2(acc2[12], h3, w0.x); fma2(acc2[13], h3, w0.y);
                fma2(acc2[14], h3, w1.x); fma2(acc2[15], h3, w1.y);
            }
            CP_WAIT0();
            __syncthreads();
            #pragma unroll
            for (int u = 4; u < 8; ++u) {
                const int k = lane + (u << 5);
                float4 hv = *(const float4*)(hb + k * HXS + bw);
                ulonglong2 w0 = *(const ulonglong2*)(ws + k * WSS);
                ulonglong2 w1 = *(const ulonglong2*)(ws + k * WSS + 4);
                ull h0 = pk2(hv.x), h1 = pk2(hv.y), h2 = pk2(hv.z), h3 = pk2(hv.w);
                fma2(acc2[0],  h0, w0.x); fma2(acc2[1],  h0, w0.y);
                fma2(acc2[2],  h0, w1.x); fma2(acc2[3],  h0, w1.y);
                fma2(acc2[4],  h1, w0.x); fma2(acc2[5],  h1, w0.y);
                fma2(acc2[6],  h1, w1.x); fma2(acc2[7],  h1, w1.y);
                fma2(acc2[8],  h2, w0.x); fma2(acc2[9],  h2, w0.y);
                fma2(acc2[10], h2, w1.x); fma2(acc2[11], h2, w1.y);
                fma2(acc2[12], h3, w0.x); fma2(acc2[13], h3, w0.y);
                fma2(acc2[14], h3, w1.x); fma2(acc2[15], h3, w1.y);
            }
        }

        // ---- packed butterfly reduce-scatter ----
        #pragma unroll
        for (int n = 16; n >= 2; n >>= 1) {
            const int m = n >> 1;
            #pragma unroll
            for (int s = 0; s < m; ++s) {
                ull lo = acc2[s], hi = acc2[s + m];
                ull send = (lane & n) ? lo : hi;
                ull keep = (lane & n) ? hi : lo;
                acc2[s] = add2(keep, __shfl_xor_sync(0xffffffffu, send, n));
            }
        }
        float pre;
        {
            unsigned u0, u1;
            asm("mov.b64 {%0, %1}, %2;" : "=r"(u0), "=r"(u1) : "l"(acc2[0]));
            float a0 = __uint_as_float(u0), a1 = __uint_as_float(u1);
            float send = (lane & 1) ? a0 : a1;
            float keep = (lane & 1) ? a1 : a0;
            pre = keep + __shfl_xor_sync(0xffffffffu, send, 1);
        }
        pre += gxv + biasv;

        // ---- gather gates, cell, write h (plain STG; release rides the flag) ----
        float pf = __shfl_sync(0xffffffffu, pre, base | (2 + jj));
        float pg = __shfl_sync(0xffffffffu, pre, base | (4 + jj));
        float po = __shfl_sync(0xffffffffu, pre, base | (6 + jj));
        if (upd) {
            float ig = 1.f / (1.f + __expf(-pre));
            float fg = 1.f / (1.f + __expf(-pf));
            float gg = tanhf(pg);
            float og = 1.f / (1.f + __expf(-po));
            creg = fg * creg + ig * gg;
            float hv = og * tanhf(creg);
            g_hbuf[(t & 1) ^ 1][(j0 + jj) * BB + myb] = hv;
            out[((size_t)myb * TT + t) * HH + (j0 + jj)] = hv;
        }
    }
}

// ============================================================
extern "C" void kernel_launch(void* const* d_in, const int* in_sizes, int n_in,
                              void* d_out, int out_size)
{
    const float* x  = (const float*)d_in[0];   // [B, T, I]
    const float* Wx = (const float*)d_in[1];   // [4, I, H]
    const float* Wh = (const float*)d_in[2];   // [4, H, H]
    const float* b  = (const float*)d_in[3];   // [4, H]
    float* out = (float*)d_out;                // [B, T, H]

    cudaFuncSetAttribute(gx_kernel,
                         cudaFuncAttributeMaxDynamicSharedMemorySize, GX_SMEM_BYTES);
    cudaFuncSetAttribute(lstm_kernel,
                         cudaFuncAttributeMaxDynamicSharedMemorySize, SMEM_BYTES);

    xpose_kernel<<<TT, 256>>>(x);
    gx_kernel<<<dim3(TT, 8), 512, GX_SMEM_BYTES>>>(Wx);
    lstm_kernel<<<NBLK, NTHR, SMEM_BYTES>>>(Wh, b, out);
}